// round 3
// baseline (speedup 1.0000x reference)
#include <cuda_runtime.h>

#define NB 8
#define SQ 2048
#define SK 2048
#define DD 512
#define DV 512

// Scratch: M[b] = K[b]^T @ V[b], [NB, DD, DV] fp32 = 8 MB
__device__ float g_M[NB * DD * DV];
// Normalized valid_len (int32), robust to int32-vs-int64 input layout
__device__ int g_vl[SQ];

// ---------------------------------------------------------------------------
// Kernel 0: normalize valid_len. Detect whether the raw buffer is int64 or
// int32: if int64 (LE), every odd int32 word among the first 2048 is a zero
// high-half; if int32, those are random values in [0,512) and the probability
// all 1024 are zero is (1/512)^1024 ~ 0.
// ---------------------------------------------------------------------------
__global__ void normalize_vlen_kernel(const int* __restrict__ raw)
{
    __shared__ int odd_nonzero;
    if (threadIdx.x == 0) odd_nonzero = 0;
    __syncthreads();

    int local = 0;
    for (int i = threadIdx.x; i < SQ; i += blockDim.x)
        if ((i & 1) && raw[i] != 0) local = 1;
    if (local) atomicOr(&odd_nonzero, 1);
    __syncthreads();

    const bool is32 = (odd_nonzero != 0);
    for (int q = threadIdx.x; q < SQ; q += blockDim.x)
        g_vl[q] = is32 ? raw[q] : raw[2 * q];
}

// ---------------------------------------------------------------------------
// Kernel A: M[b] = K[b]^T @ V[b]
//   C[d, v] = sum_s K[s, d] * V[s, v]
//   64x64 output tile, 256 threads, 4x4 per thread, K-chunk = 16
// ---------------------------------------------------------------------------
__global__ __launch_bounds__(256) void ktv_kernel(
    const float* __restrict__ K, const float* __restrict__ V)
{
    __shared__ float Ks[16][64];  // [s][d]
    __shared__ float Vs[16][64];  // [s][v]

    const int b  = blockIdx.z;
    const int d0 = blockIdx.y * 64;
    const int v0 = blockIdx.x * 64;

    const float* __restrict__ Kb = K + (size_t)b * SK * DD;
    const float* __restrict__ Vb = V + (size_t)b * SK * DV;

    const int tid = threadIdx.x;
    const int tx  = tid % 16;       // col group (v)
    const int ty  = tid / 16;       // row group (d)

    const int lrow = tid / 16;          // 0..15 (s within chunk)
    const int lcol = (tid % 16) * 4;    // 0..60

    float acc[4][4] = {};

    for (int s0 = 0; s0 < SK; s0 += 16) {
        *(float4*)&Ks[lrow][lcol] = *(const float4*)&Kb[(size_t)(s0 + lrow) * DD + d0 + lcol];
        *(float4*)&Vs[lrow][lcol] = *(const float4*)&Vb[(size_t)(s0 + lrow) * DV + v0 + lcol];
        __syncthreads();

#pragma unroll
        for (int kk = 0; kk < 16; kk++) {
            const float4 av = *(const float4*)&Ks[kk][ty * 4];
            const float4 bv = *(const float4*)&Vs[kk][tx * 4];
            acc[0][0] += av.x * bv.x; acc[0][1] += av.x * bv.y; acc[0][2] += av.x * bv.z; acc[0][3] += av.x * bv.w;
            acc[1][0] += av.y * bv.x; acc[1][1] += av.y * bv.y; acc[1][2] += av.y * bv.z; acc[1][3] += av.y * bv.w;
            acc[2][0] += av.z * bv.x; acc[2][1] += av.z * bv.y; acc[2][2] += av.z * bv.z; acc[2][3] += av.z * bv.w;
            acc[3][0] += av.w * bv.x; acc[3][1] += av.w * bv.y; acc[3][2] += av.w * bv.z; acc[3][3] += av.w * bv.w;
        }
        __syncthreads();
    }

    float* __restrict__ Mb = g_M + (size_t)b * DD * DV;
#pragma unroll
    for (int i = 0; i < 4; i++) {
        float4 w = make_float4(acc[i][0], acc[i][1], acc[i][2], acc[i][3]);
        *(float4*)&Mb[(size_t)(d0 + ty * 4 + i) * DV + v0 + tx * 4] = w;
    }
}

// ---------------------------------------------------------------------------
// Kernel B: X = Q @ M * (1/sqrt(512)); then mask (col > valid_len[q] -> -1e6)
//           and row softmax over the 512 columns — all fused.
//   Block: 256 threads = 8 warps; block tile = 32 rows x 512 cols.
//   Each warp owns 4 rows; lane l owns cols {l, l+32, ..., l+480} (16 cols).
//   Softmax reductions are warp-shfl only; writes fully coalesced.
// ---------------------------------------------------------------------------
__global__ __launch_bounds__(256) void qm_softmax_kernel(
    const float* __restrict__ Q, float* __restrict__ out)
{
    __shared__ float Ms[16][DV];   // 32 KB : [k][v]
    __shared__ float Qs[32][16];   //  2 KB : [row][k]

    const int b  = blockIdx.y;
    const int q0 = blockIdx.x * 32;

    const int tid  = threadIdx.x;
    const int lane = tid & 31;
    const int warp = tid >> 5;       // 0..7
    const int r0   = warp * 4;       // local row base for this warp

    const float* __restrict__ Qb = Q   + (size_t)b * SQ * DD;
    const float* __restrict__ Mb = g_M + (size_t)b * DD * DV;

    float acc[4][16] = {};

    for (int k0 = 0; k0 < DD; k0 += 16) {
        // load Ms: 16x512 floats = 2048 float4, 8 per thread
#pragma unroll
        for (int i = 0; i < 8; i++) {
            int f    = tid + i * 256;         // float4 linear index
            int row  = f >> 7;                // / 128 (128 float4 per row)
            int col4 = f & 127;
            *(float4*)&Ms[row][col4 * 4] =
                *(const float4*)&Mb[(size_t)(k0 + row) * DV + col4 * 4];
        }
        // load Qs: 32x16 floats = 128 float4 (threads 0..127)
        if (tid < 128) {
            int row  = tid >> 2;
            int col4 = tid & 3;
            *(float4*)&Qs[row][col4 * 4] =
                *(const float4*)&Qb[(size_t)(q0 + row) * DD + k0 + col4 * 4];
        }
        __syncthreads();

#pragma unroll
        for (int kk = 0; kk < 16; kk++) {
            const float a0 = Qs[r0 + 0][kk];
            const float a1 = Qs[r0 + 1][kk];
            const float a2 = Qs[r0 + 2][kk];
            const float a3 = Qs[r0 + 3][kk];
#pragma unroll
            for (int j = 0; j < 16; j++) {
                const float bv = Ms[kk][lane + 32 * j];
                acc[0][j] += a0 * bv;
                acc[1][j] += a1 * bv;
                acc[2][j] += a2 * bv;
                acc[3][j] += a3 * bv;
            }
        }
        __syncthreads();
    }

    const float scale = 0.044194173824159216f;  // 1/sqrt(512)

#pragma unroll
    for (int i = 0; i < 4; i++) {
        const int q  = q0 + r0 + i;                // global query row
        const int vl = g_vl[q];

        // scale + mask + row max
        float rmax = -3.402823e38f;
#pragma unroll
        for (int j = 0; j < 16; j++) {
            const int c = lane + 32 * j;
            float x = acc[i][j] * scale;
            if (c > vl) x = -1000000.0f;
            acc[i][j] = x;
            rmax = fmaxf(rmax, x);
        }
#pragma unroll
        for (int off = 16; off > 0; off >>= 1)
            rmax = fmaxf(rmax, __shfl_xor_sync(0xFFFFFFFFu, rmax, off));

        // exp + row sum
        float rsum = 0.0f;
#pragma unroll
        for (int j = 0; j < 16; j++) {
            const float e = __expf(acc[i][j] - rmax);
            acc[i][j] = e;
            rsum += e;
        }
#pragma unroll
        for (int off = 16; off > 0; off >>= 1)
            rsum += __shfl_xor_sync(0xFFFFFFFFu, rsum, off);

        const float inv = 1.0f / rsum;
        float* __restrict__ orow = out + (size_t)b * SQ * DV + (size_t)q * DV;
#pragma unroll
        for (int j = 0; j < 16; j++)
            orow[lane + 32 * j] = acc[i][j] * inv;
    }
}

extern "C" void kernel_launch(void* const* d_in, const int* in_sizes, int n_in,
                              void* d_out, int out_size)
{
    const float* K   = (const float*)d_in[0];
    const float* V   = (const float*)d_in[1];
    const float* Q   = (const float*)d_in[2];
    const int*   vlr = (const int*)d_in[3];
    float*       out = (float*)d_out;

    normalize_vlen_kernel<<<1, 1024>>>(vlr);

    dim3 gA(DV / 64, DD / 64, NB);   // (8, 8, 8)
    ktv_kernel<<<gA, 256>>>(K, V);

    dim3 gB(SQ / 32, NB);            // (64, 8)
    qm_softmax_kernel<<<gB, 256>>>(Q, out);
}

// round 8
// speedup vs baseline: 1.3391x; 1.3391x over previous
#include <cuda_runtime.h>
#include <cstdint>

#define NB 8
#define SQ 2048
#define SK 2048
#define DD 512
#define DV 512
#define LDW 512       // all matrices have 512-float rows
#define TSTRIDE 36    // smem tile row stride in floats (conflict-free frag loads)

__device__ float g_MT[NB * DV * DD];   // MT[b][v][d] = sum_s V[s,v]*K[s,d]
__device__ float g_X [NB * SQ * DV];   // X[b][q][v]  = (Q @ MT^T)/sqrt(512)
__device__ int   g_vl[SQ];

// ---------------------------------------------------------------------------
// tf32 helpers
// ---------------------------------------------------------------------------
__device__ __forceinline__ void split2(float x, uint32_t& h, uint32_t& l) {
    asm("cvt.rna.tf32.f32 %0, %1;" : "=r"(h) : "f"(x));
    float r = x - __uint_as_float(h);
    asm("cvt.rna.tf32.f32 %0, %1;" : "=r"(l) : "f"(r));
}
__device__ __forceinline__ void split4(float4 g, uint4& h, uint4& l) {
    split2(g.x, h.x, l.x); split2(g.y, h.y, l.y);
    split2(g.z, h.z, l.z); split2(g.w, h.w, l.w);
}

// D += A * B^T : m16n8k8 tf32 (A row-major 16x8, B "col-major" = [n][k])
#define MMA(c, a, b) asm volatile( \
    "mma.sync.aligned.m16n8k8.row.col.f32.tf32.tf32.f32 " \
    "{%0,%1,%2,%3}, {%4,%5,%6,%7}, {%8,%9}, {%0,%1,%2,%3};" \
    : "+f"((c)[0]), "+f"((c)[1]), "+f"((c)[2]), "+f"((c)[3]) \
    : "r"((a)[0]), "r"((a)[1]), "r"((a)[2]), "r"((a)[3]), \
      "r"((b)[0]), "r"((b)[1]))

// Fragment loads from smem tile laid out [row][k], stride TSTRIDE floats.
// m16n8k8 A frag: a0=(g, t) a1=(g+8, t) a2=(g, t+4) a3=(g+8, t+4);
//                 g = lane>>2 (row), t = lane&3 (k)
__device__ __forceinline__ void ldfragA(const float* T, int r0, int k0, int lane,
                                        uint32_t a[4]) {
    const float* p = T + (size_t)(r0 + (lane >> 2)) * TSTRIDE + k0 + (lane & 3);
    a[0] = __float_as_uint(p[0]);
    a[1] = __float_as_uint(p[8 * TSTRIDE]);
    a[2] = __float_as_uint(p[4]);
    a[3] = __float_as_uint(p[8 * TSTRIDE + 4]);
}
// B frag: b0=(n=g, k=t) b1=(n=g, k=t+4)
__device__ __forceinline__ void ldfragB(const float* T, int n0, int k0, int lane,
                                        uint32_t b[2]) {
    const float* p = T + (size_t)(n0 + (lane >> 2)) * TSTRIDE + k0 + (lane & 3);
    b[0] = __float_as_uint(p[0]);
    b[1] = __float_as_uint(p[4]);
}

// ---------------------------------------------------------------------------
// Kernel 0: normalize valid_len (autodetect int64 vs int32 buffer layout)
// ---------------------------------------------------------------------------
__global__ void normalize_vlen_kernel(const int* __restrict__ raw)
{
    __shared__ int odd_nonzero;
    if (threadIdx.x == 0) odd_nonzero = 0;
    __syncthreads();
    int local = 0;
    for (int i = threadIdx.x; i < SQ; i += blockDim.x)
        if ((i & 1) && raw[i] != 0) local = 1;
    if (local) atomicOr(&odd_nonzero, 1);
    __syncthreads();
    const bool is32 = (odd_nonzero != 0);
    for (int q = threadIdx.x; q < SQ; q += blockDim.x)
        g_vl[q] = is32 ? raw[q] : raw[2 * q];
}

// ---------------------------------------------------------------------------
// tf32x3 GEMM via mma.sync, CTA tile 128x128, k-chunk 32.
//   C[m][n] = csc * sum_k A'[m][k] * B'[n][k]
//   TRANS=1 (kernel A): A' = V^T, B' = K^T (gmem [k][x], transpose-on-load)
//   TRANS=0 (kernel B): A' = Q,   B' = MT  (gmem [x][k], straight load)
// 8 warps as 2(m) x 4(n); warp tile 64x32 = 4x4 m16n8k8 atoms.
// ---------------------------------------------------------------------------
template <int TRANS>
__global__ __launch_bounds__(256, 2) void gemm_mma(
    const float* __restrict__ p0, const float* __restrict__ p1)
{
    extern __shared__ float smf[];
    float* Ah = smf;
    float* Al = smf + 128 * TSTRIDE;
    float* Bh = smf + 2 * 128 * TSTRIDE;
    float* Bl = smf + 3 * 128 * TSTRIDE;

    const int tid = threadIdx.x, lane = tid & 31, wid = tid >> 5;
    const int wm = wid >> 2, wn = wid & 3;       // warp grid 2 x 4
    const int n0 = blockIdx.x * 128, m0 = blockIdx.y * 128, b = blockIdx.z;

    const float* __restrict__ Ag;
    const float* __restrict__ Bg;
    float* __restrict__ Cb;
    int kT; float csc;
    if (TRANS) {   // A=V [s][v], B=K [s][d], C=g_MT [v][d]
        Ag = p0 + (size_t)b * SK * DV;  Bg = p1 + (size_t)b * SK * DD;
        Cb = g_MT + (size_t)b * DV * DD;  kT = SK;  csc = 1.0f;
    } else {       // A=Q [q][d], B=g_MT [v][d], C=g_X [q][v]
        Ag = p0 + (size_t)b * SQ * DD;  Bg = g_MT + (size_t)b * DV * DD;
        Cb = g_X + (size_t)b * SQ * DV;  kT = DD;  csc = 0.044194173824159216f;
    }

    float c[4][4][4];
#pragma unroll
    for (int i = 0; i < 4; i++)
#pragma unroll
        for (int j = 0; j < 4; j++)
#pragma unroll
            for (int u = 0; u < 4; u++) c[i][j][u] = 0.0f;

    const int nch = kT / 32;
    for (int ch = 0; ch < nch; ch++) {
        const int k0 = ch * 32;

        // ---- issue gmem loads BEFORE the barrier (latency overlap) ----
        float4 ga[4], gb[4];
        if (TRANS) {
            const int s = 4 * (lane & 7);              // k within chunk
            const int x = 16 * wid + 4 * (lane >> 3);  // m/n within tile
#pragma unroll
            for (int i = 0; i < 4; i++) {
                ga[i] = *(const float4*)&Ag[(size_t)(k0 + s + i) * LDW + m0 + x];
                gb[i] = *(const float4*)&Bg[(size_t)(k0 + s + i) * LDW + n0 + x];
            }
        } else {
#pragma unroll
            for (int i = 0; i < 4; i++) {
                const int f = tid + i * 256;           // float4 idx: 128 rows x 8
                const int row = f >> 3, col4 = f & 7;
                ga[i] = *(const float4*)&Ag[(size_t)(m0 + row) * LDW + k0 + col4 * 4];
                gb[i] = *(const float4*)&Bg[(size_t)(n0 + row) * LDW + k0 + col4 * 4];
            }
        }

        if (ch > 0) __syncthreads();   // previous chunk's MMAs done with smem

        // ---- split + store to smem tiles ----
        if (TRANS) {
            const int s = 4 * (lane & 7);
            const int x = 16 * wid + 4 * (lane >> 3);
            const float* fa = (const float*)ga;
            const float* fb = (const float*)gb;
#pragma unroll
            for (int j = 0; j < 4; j++) {
                float4 colA = make_float4(fa[j], fa[4 + j], fa[8 + j], fa[12 + j]);
                float4 colB = make_float4(fb[j], fb[4 + j], fb[8 + j], fb[12 + j]);
                uint4 h, l;
                split4(colA, h, l);
                *(uint4*)&Ah[(size_t)(x + j) * TSTRIDE + s] = h;
                *(uint4*)&Al[(size_t)(x + j) * TSTRIDE + s] = l;
                split4(colB, h, l);
                *(uint4*)&Bh[(size_t)(x + j) * TSTRIDE + s] = h;
                *(uint4*)&Bl[(size_t)(x + j) * TSTRIDE + s] = l;
            }
        } else {
#pragma unroll
            for (int i = 0; i < 4; i++) {
                const int f = tid + i * 256;
                const int row = f >> 3, col4 = f & 7;
                uint4 h, l;
                split4(ga[i], h, l);
                *(uint4*)&Ah[(size_t)row * TSTRIDE + col4 * 4] = h;
                *(uint4*)&Al[(size_t)row * TSTRIDE + col4 * 4] = l;
                split4(gb[i], h, l);
                *(uint4*)&Bh[(size_t)row * TSTRIDE + col4 * 4] = h;
                *(uint4*)&Bl[(size_t)row * TSTRIDE + col4 * 4] = l;
            }
        }
        __syncthreads();

        // ---- MMA: 4 k-steps of 8, tf32x3 ----
#pragma unroll
        for (int ks = 0; ks < 4; ks++) {
            const int kk = ks * 8;
            uint32_t bh[4][2], bl[4][2];
#pragma unroll
            for (int an = 0; an < 4; an++) {
                const int nb = wn * 32 + an * 8;
                ldfragB(Bh, nb, kk, lane, bh[an]);
                ldfragB(Bl, nb, kk, lane, bl[an]);
            }
#pragma unroll
            for (int am = 0; am < 4; am++) {
                const int mr = wm * 64 + am * 16;
                uint32_t ah[4], al[4];
                ldfragA(Ah, mr, kk, lane, ah);
                ldfragA(Al, mr, kk, lane, al);
#pragma unroll
                for (int an = 0; an < 4; an++) {
                    MMA(c[am][an], ah, bh[an]);
                    MMA(c[am][an], al, bh[an]);
                    MMA(c[am][an], ah, bl[an]);
                }
            }
        }
    }

    // ---- epilogue: c frag -> gmem ----
#pragma unroll
    for (int am = 0; am < 4; am++) {
        const int mr = m0 + wm * 64 + am * 16 + (lane >> 2);
#pragma unroll
        for (int an = 0; an < 4; an++) {
            const int nc = n0 + wn * 32 + an * 8 + (lane & 3) * 2;
            float2 w0 = make_float2(c[am][an][0] * csc, c[am][an][1] * csc);
            float2 w1 = make_float2(c[am][an][2] * csc, c[am][an][3] * csc);
            *(float2*)&Cb[(size_t)mr * LDW + nc]       = w0;
            *(float2*)&Cb[(size_t)(mr + 8) * LDW + nc] = w1;
        }
    }
}

// ---------------------------------------------------------------------------
// Kernel C: mask (col > valid_len[q] -> -1e6) + row softmax over 512 cols.
// ---------------------------------------------------------------------------
__global__ __launch_bounds__(256) void softmax_kernel(float* __restrict__ out)
{
    const int b = blockIdx.y, q0 = blockIdx.x * 32;
    const int tid = threadIdx.x, lane = tid & 31, warp = tid >> 5;
    const int r0 = warp * 4;
    const float* __restrict__ Xb = g_X + (size_t)b * SQ * DV;

    float acc[4][16];
#pragma unroll
    for (int i = 0; i < 4; i++) {
        const float* row = Xb + (size_t)(q0 + r0 + i) * DV;
#pragma unroll
        for (int j = 0; j < 16; j++) acc[i][j] = row[lane + 32 * j];
    }

#pragma unroll
    for (int i = 0; i < 4; i++) {
        const int q = q0 + r0 + i;
        const int vl = g_vl[q];
        float rmax = -3.402823e38f;
#pragma unroll
        for (int j = 0; j < 16; j++) {
            const int cidx = lane + 32 * j;
            float x = acc[i][j];
            if (cidx > vl) x = -1000000.0f;
            acc[i][j] = x;
            rmax = fmaxf(rmax, x);
        }
#pragma unroll
        for (int off = 16; off > 0; off >>= 1)
            rmax = fmaxf(rmax, __shfl_xor_sync(0xFFFFFFFFu, rmax, off));
        float rsum = 0.0f;
#pragma unroll
        for (int j = 0; j < 16; j++) {
            const float e = __expf(acc[i][j] - rmax);
            acc[i][j] = e;
            rsum += e;
        }
#pragma unroll
        for (int off = 16; off > 0; off >>= 1)
            rsum += __shfl_xor_sync(0xFFFFFFFFu, rsum, off);
        const float inv = 1.0f / rsum;
        float* __restrict__ orow = out + (size_t)b * SQ * DV + (size_t)q * DV;
#pragma unroll
        for (int j = 0; j < 16; j++)
            orow[lane + 32 * j] = acc[i][j] * inv;
    }
}

#define GEMM_SMEM (4 * 128 * TSTRIDE * 4)   // 73728 bytes

extern "C" void kernel_launch(void* const* d_in, const int* in_sizes, int n_in,
                              void* d_out, int out_size)
{
    const float* K   = (const float*)d_in[0];
    const float* V   = (const float*)d_in[1];
    const float* Q   = (const float*)d_in[2];
    const int*   vlr = (const int*)d_in[3];
    float*       out = (float*)d_out;

    cudaFuncSetAttribute(gemm_mma<1>, cudaFuncAttributeMaxDynamicSharedMemorySize, GEMM_SMEM);
    cudaFuncSetAttribute(gemm_mma<0>, cudaFuncAttributeMaxDynamicSharedMemorySize, GEMM_SMEM);

    normalize_vlen_kernel<<<1, 1024>>>(vlr);

    dim3 gA(DD / 128, DV / 128, NB);                 // (4, 4, 8): MT[v][d]
    gemm_mma<1><<<gA, 256, GEMM_SMEM>>>(V, K);

    dim3 gB(DV / 128, SQ / 128, NB);                 // (4, 16, 8): X[q][v]
    gemm_mma<0><<<gB, 256, GEMM_SMEM>>>(Q, nullptr);

    dim3 gC(SQ / 32, NB);                            // (64, 8)
    softmax_kernel<<<gC, 256>>>(out);
}